// round 4
// baseline (speedup 1.0000x reference)
#include <cuda_runtime.h>
#include <cstdint>

#define SEQ    2048
#define BATCH  4096
#define IN     4
#define HID    3
#define UNR    8                  // timesteps per group/phase
#define NGRP   (SEQ / UNR)        // 256
#define PS     4                  // p-ring slots
#define HS     2                  // h-ring slots

__global__ void __launch_bounds__(128, 1)
rnn_relu_kernel(const float* __restrict__ x,      // [SEQ, BATCH, 4]
                const float* __restrict__ h0,     // [1, BATCH, 3]
                const float* __restrict__ W_ih,   // [3, 4]
                const float* __restrict__ W_hh,   // [3, 3]
                const float* __restrict__ b_ih,   // [3]
                const float* __restrict__ b_hh,   // [3]
                float* __restrict__ out)
{
    // p-ring: projections (p0,p1,p2,pad). h-ring: hidden states (h0,h1,h2,pad).
    __shared__ float4 pring[PS][UNR][32];   // 16 KB
    __shared__ float4 hring[HS][UNR][32];   //  8 KB

    const int lane = threadIdx.x & 31;
    const int warp = threadIdx.x >> 5;
    const int b0   = blockIdx.x * 32;
    const int b    = b0 + lane;

    const float4* __restrict__ xv = (const float4*)x;   // [SEQ][BATCH]
    float* __restrict__ outs  = out;
    float* __restrict__ hlast = out + (size_t)SEQ * BATCH * HID;

    if (warp == 0) {
        // ================= compute warp: recurrence only =================
        float whh[HID][HID];
#pragma unroll
        for (int j = 0; j < HID; j++)
#pragma unroll
            for (int i = 0; i < HID; i++) whh[j][i] = W_hh[j * HID + i];

        float ha = h0[b * HID + 0];
        float hb = h0[b * HID + 1];
        float hc = h0[b * HID + 2];

        __syncthreads();  // bar#0: p[0] published

        for (int gg = 0; gg < NGRP; gg += 4) {
#pragma unroll
            for (int gi = 0; gi < 4; gi++) {
                const int g = gg + gi;
#pragma unroll
                for (int k = 0; k < UNR; k++) {
                    const float4 p = pring[g & (PS - 1)][k][lane];  // indep of h -> hoisted

                    float a0 = fmaf(whh[0][0], ha, p.x);
                    float a1 = fmaf(whh[1][0], ha, p.y);
                    float a2 = fmaf(whh[2][0], ha, p.z);
                    a0 = fmaf(whh[0][1], hb, a0);
                    a1 = fmaf(whh[1][1], hb, a1);
                    a2 = fmaf(whh[2][1], hb, a2);
                    a0 = fmaf(whh[0][2], hc, a0);
                    a1 = fmaf(whh[1][2], hc, a1);
                    a2 = fmaf(whh[2][2], hc, a2);

                    ha = fmaxf(a0, 0.0f);
                    hb = fmaxf(a1, 0.0f);
                    hc = fmaxf(a2, 0.0f);

                    hring[g & (HS - 1)][k][lane] = make_float4(ha, hb, hc, 0.0f);
                }
                __syncthreads();  // bar#(g+1): h[g] + p[g+1] published
            }
        }

        hlast[b * HID + 0] = ha;
        hlast[b * HID + 1] = hb;
        hlast[b * HID + 2] = hc;

    } else if (warp <= 2) {
        // ================= producer warps: x load + projection =================
        float wih[HID][IN];
        float bias[HID];
#pragma unroll
        for (int j = 0; j < HID; j++) {
#pragma unroll
            for (int i = 0; i < IN; i++) wih[j][i] = W_ih[j * IN + i];
            bias[j] = b_ih[j] + b_hh[j];
        }

        const int tbase = (warp - 1) * 4;   // warp1: t 0..3, warp2: t 4..7

        // Rolling x registers: xr[(g)&3] holds x for group g (4 timesteps).
        float4 xr[4][4];

        // ---- prime: x[0..3], p[0] ----
        float4 x0[4];
#pragma unroll
        for (int i = 0; i < 4; i++)
            x0[i] = xv[(size_t)(0 * UNR + tbase + i) * BATCH + b];
#pragma unroll
        for (int s = 1; s < 4; s++)
#pragma unroll
            for (int i = 0; i < 4; i++)
                xr[s][i] = xv[(size_t)(s * UNR + tbase + i) * BATCH + b];

#pragma unroll
        for (int i = 0; i < 4; i++) {
            const float4 xt = x0[i];
            float4 p;
            p.x = fmaf(wih[0][0], xt.x, bias[0]);
            p.y = fmaf(wih[1][0], xt.x, bias[1]);
            p.z = fmaf(wih[2][0], xt.x, bias[2]);
            p.x = fmaf(wih[0][1], xt.y, p.x);
            p.y = fmaf(wih[1][1], xt.y, p.y);
            p.z = fmaf(wih[2][1], xt.y, p.z);
            p.x = fmaf(wih[0][2], xt.z, p.x);
            p.y = fmaf(wih[1][2], xt.z, p.y);
            p.z = fmaf(wih[2][2], xt.z, p.z);
            p.x = fmaf(wih[0][3], xt.w, p.x);
            p.y = fmaf(wih[1][3], xt.w, p.y);
            p.z = fmaf(wih[2][3], xt.w, p.z);
            p.w = 0.0f;
            pring[0][tbase + i][lane] = p;
        }
        __syncthreads();  // bar#0

        for (int gg = 0; gg < NGRP; gg += 4) {
#pragma unroll
            for (int gi = 0; gi < 4; gi++) {
                const int g = gg + gi;

                // Issue LDG for group g+4 (clamped) into xr[g&3] ((g+4)&3 == g&3).
                // Non-blocking: never waited on before the barrier.
                const int gl = (g + 4 < NGRP) ? (g + 4) : (NGRP - 1);
#pragma unroll
                for (int i = 0; i < 4; i++)
                    xr[g & 3][i] = xv[(size_t)(gl * UNR + tbase + i) * BATCH + b];

                // Projection for group g+1 from x loaded 3 phases ago (~700 cyc slack).
                if (g + 1 < NGRP) {
#pragma unroll
                    for (int i = 0; i < 4; i++) {
                        const float4 xt = xr[(g + 1) & 3][i];
                        float4 p;
                        p.x = fmaf(wih[0][0], xt.x, bias[0]);
                        p.y = fmaf(wih[1][0], xt.x, bias[1]);
                        p.z = fmaf(wih[2][0], xt.x, bias[2]);
                        p.x = fmaf(wih[0][1], xt.y, p.x);
                        p.y = fmaf(wih[1][1], xt.y, p.y);
                        p.z = fmaf(wih[2][1], xt.y, p.z);
                        p.x = fmaf(wih[0][2], xt.z, p.x);
                        p.y = fmaf(wih[1][2], xt.z, p.y);
                        p.z = fmaf(wih[2][2], xt.z, p.z);
                        p.x = fmaf(wih[0][3], xt.w, p.x);
                        p.y = fmaf(wih[1][3], xt.w, p.y);
                        p.z = fmaf(wih[2][3], xt.w, p.z);
                        p.w = 0.0f;
                        pring[(g + 1) & (PS - 1)][tbase + i][lane] = p;
                    }
                }
                __syncthreads();  // bar#(g+1)
            }
        }

    } else {
        // ================= storer warp: drain h-ring to gmem =================
        // lane L < 24 handles output floats [4L, 4L+4) of each 96-float (t) row.
        int idx[4];
#pragma unroll
        for (int j = 0; j < 4; j++) {
            const int f = 4 * lane + j;          // flat float index in row
            idx[j] = (f / 3) * 4 + (f % 3);      // index into padded float4 row
        }

        __syncthreads();  // bar#0

        for (int gg = 0; gg < NGRP; gg += 4) {
#pragma unroll
            for (int gi = 0; gi < 4; gi++) {
                const int g = gg + gi;
                if (g >= 1 && lane < 24) {
                    const int gd = g - 1;
                    const float* hb_ = (const float*)&hring[gd & (HS - 1)][0][0];
#pragma unroll
                    for (int k = 0; k < UNR; k++) {
                        const float* row = hb_ + k * 128;  // 32 float4 = 128 floats
                        float4 v;
                        v.x = row[idx[0]];
                        v.y = row[idx[1]];
                        v.z = row[idx[2]];
                        v.w = row[idx[3]];
                        *(float4*)(outs + ((size_t)(gd * UNR + k) * BATCH + b0) * HID
                                   + lane * 4) = v;
                    }
                }
                __syncthreads();  // bar#(g+1)
            }
        }

        // Final group drain (h[NGRP-1] published at the last barrier).
        if (lane < 24) {
            const int gd = NGRP - 1;
            const float* hb_ = (const float*)&hring[gd & (HS - 1)][0][0];
#pragma unroll
            for (int k = 0; k < UNR; k++) {
                const float* row = hb_ + k * 128;
                float4 v;
                v.x = row[idx[0]];
                v.y = row[idx[1]];
                v.z = row[idx[2]];
                v.w = row[idx[3]];
                *(float4*)(outs + ((size_t)(gd * UNR + k) * BATCH + b0) * HID
                           + lane * 4) = v;
            }
        }
    }
}

extern "C" void kernel_launch(void* const* d_in, const int* in_sizes, int n_in,
                              void* d_out, int out_size)
{
    const float* x    = (const float*)d_in[0];
    const float* h0   = (const float*)d_in[1];
    const float* W_ih = (const float*)d_in[2];
    const float* W_hh = (const float*)d_in[3];
    const float* b_ih = (const float*)d_in[4];
    const float* b_hh = (const float*)d_in[5];
    float* out = (float*)d_out;

    // 128 blocks x 128 threads: 4 specialized warps per block, one per SMSP.
    rnn_relu_kernel<<<BATCH / 32, 128>>>(x, h0, W_ih, W_hh, b_ih, b_hh, out);
}

// round 5
// speedup vs baseline: 1.0121x; 1.0121x over previous
#include <cuda_runtime.h>
#include <cstdint>

#define SEQ    2048
#define BATCH  4096
#define IN     4
#define HID    3
#define PF     16                  // prefetch depth (iters) = rolling x regs
#define NGRP   (SEQ / PF)          // 128 groups of 16 timesteps

__global__ void __launch_bounds__(32, 1)
rnn_relu_kernel(const float* __restrict__ x,      // [SEQ, BATCH, 4]
                const float* __restrict__ h0,     // [1, BATCH, 3]
                const float* __restrict__ W_ih,   // [3, 4]
                const float* __restrict__ W_hh,   // [3, 3]
                const float* __restrict__ b_ih,   // [3]
                const float* __restrict__ b_hh,   // [3]
                float* __restrict__ out)
{
    const int b = blockIdx.x * 32 + threadIdx.x;

    // Uniform weights/biases in registers.
    float wih[HID][IN];
    float whh[HID][HID];
    float bias[HID];
#pragma unroll
    for (int j = 0; j < HID; j++) {
#pragma unroll
        for (int i = 0; i < IN; i++) wih[j][i] = W_ih[j * IN + i];
#pragma unroll
        for (int i = 0; i < HID; i++) whh[j][i] = W_hh[j * HID + i];
        bias[j] = b_ih[j] + b_hh[j];
    }

    float ha = h0[b * HID + 0];
    float hb = h0[b * HID + 1];
    float hc = h0[b * HID + 2];

    const float4* __restrict__ xv = (const float4*)x;  // [SEQ][BATCH]
    float* __restrict__ outs  = out;
    float* __restrict__ hlast = out + (size_t)SEQ * BATCH * HID;

    // Rolling register prefetch buffer: xr[k] holds x[t] for the current
    // group's timestep k; refilled immediately after consumption with x[t+PF].
    float4 xr[PF];
#pragma unroll
    for (int k = 0; k < PF; k++)
        xr[k] = xv[(size_t)k * BATCH + b];

    // Main loop: groups 0..NGRP-2 prefetch the next group; last group peeled.
    for (int g = 0; g < NGRP - 1; g++) {
        const int t0 = g * PF;
#pragma unroll
        for (int k = 0; k < PF; k++) {
            const float4 xt = xr[k];
            // Refill this slot ~PF iterations (~670 cyc) before next use.
            xr[k] = xv[(size_t)(t0 + PF + k) * BATCH + b];

            // Input projection (off the serial chain).
            float p0 = fmaf(wih[0][0], xt.x, bias[0]);
            float p1 = fmaf(wih[1][0], xt.x, bias[1]);
            float p2 = fmaf(wih[2][0], xt.x, bias[2]);
            p0 = fmaf(wih[0][1], xt.y, p0);
            p1 = fmaf(wih[1][1], xt.y, p1);
            p2 = fmaf(wih[2][1], xt.y, p2);
            p0 = fmaf(wih[0][2], xt.z, p0);
            p1 = fmaf(wih[1][2], xt.z, p1);
            p2 = fmaf(wih[2][2], xt.z, p2);
            p0 = fmaf(wih[0][3], xt.w, p0);
            p1 = fmaf(wih[1][3], xt.w, p1);
            p2 = fmaf(wih[2][3], xt.w, p2);

            // Recurrent update (serial chain: 3 FFMA + max = ~16 cyc).
            float a0 = fmaf(whh[0][0], ha, p0);
            float a1 = fmaf(whh[1][0], ha, p1);
            float a2 = fmaf(whh[2][0], ha, p2);
            a0 = fmaf(whh[0][1], hb, a0);
            a1 = fmaf(whh[1][1], hb, a1);
            a2 = fmaf(whh[2][1], hb, a2);
            a0 = fmaf(whh[0][2], hc, a0);
            a1 = fmaf(whh[1][2], hc, a1);
            a2 = fmaf(whh[2][2], hc, a2);

            ha = fmaxf(a0, 0.0f);
            hb = fmaxf(a1, 0.0f);
            hc = fmaxf(a2, 0.0f);

            const size_t o = ((size_t)(t0 + k) * BATCH + b) * HID;
            outs[o + 0] = ha;
            outs[o + 1] = hb;
            outs[o + 2] = hc;
        }
    }

    // Peeled last group: consume remaining xr, no prefetch.
    {
        const int t0 = (NGRP - 1) * PF;
#pragma unroll
        for (int k = 0; k < PF; k++) {
            const float4 xt = xr[k];

            float p0 = fmaf(wih[0][0], xt.x, bias[0]);
            float p1 = fmaf(wih[1][0], xt.x, bias[1]);
            float p2 = fmaf(wih[2][0], xt.x, bias[2]);
            p0 = fmaf(wih[0][1], xt.y, p0);
            p1 = fmaf(wih[1][1], xt.y, p1);
            p2 = fmaf(wih[2][1], xt.y, p2);
            p0 = fmaf(wih[0][2], xt.z, p0);
            p1 = fmaf(wih[1][2], xt.z, p1);
            p2 = fmaf(wih[2][2], xt.z, p2);
            p0 = fmaf(wih[0][3], xt.w, p0);
            p1 = fmaf(wih[1][3], xt.w, p1);
            p2 = fmaf(wih[2][3], xt.w, p2);

            float a0 = fmaf(whh[0][0], ha, p0);
            float a1 = fmaf(whh[1][0], ha, p1);
            float a2 = fmaf(whh[2][0], ha, p2);
            a0 = fmaf(whh[0][1], hb, a0);
            a1 = fmaf(whh[1][1], hb, a1);
            a2 = fmaf(whh[2][1], hb, a2);
            a0 = fmaf(whh[0][2], hc, a0);
            a1 = fmaf(whh[1][2], hc, a1);
            a2 = fmaf(whh[2][2], hc, a2);

            ha = fmaxf(a0, 0.0f);
            hb = fmaxf(a1, 0.0f);
            hc = fmaxf(a2, 0.0f);

            const size_t o = ((size_t)(t0 + k) * BATCH + b) * HID;
            outs[o + 0] = ha;
            outs[o + 1] = hb;
            outs[o + 2] = hc;
        }
    }

    hlast[b * HID + 0] = ha;
    hlast[b * HID + 1] = hb;
    hlast[b * HID + 2] = hc;
}

extern "C" void kernel_launch(void* const* d_in, const int* in_sizes, int n_in,
                              void* d_out, int out_size)
{
    const float* x    = (const float*)d_in[0];
    const float* h0   = (const float*)d_in[1];
    const float* W_ih = (const float*)d_in[2];
    const float* W_hh = (const float*)d_in[3];
    const float* b_ih = (const float*)d_in[4];
    const float* b_hh = (const float*)d_in[5];
    float* out = (float*)d_out;

    // One chain per thread, one warp per block -> sync-free, self-contained warps.
    rnn_relu_kernel<<<BATCH / 32, 32>>>(x, h0, W_ih, W_hh, b_ih, b_hh, out);
}

// round 6
// speedup vs baseline: 1.9389x; 1.9158x over previous
#include <cuda_runtime.h>
#include <cstdint>

#define SEQ    2048
#define BATCH  4096
#define IN     4
#define HID    3
#define UNR    16                 // timesteps per pipeline stage
#define STAGES 4                  // smem pipeline depth (32 KB)
#define NGRP   (SEQ / UNR)        // 128 groups

typedef unsigned long long u64;

// ---- packed f32x2 helpers (Blackwell) ----
__device__ __forceinline__ u64 pack2(float lo, float hi) {
    u64 r; asm("mov.b64 %0, {%1, %2};" : "=l"(r) : "f"(lo), "f"(hi)); return r;
}
__device__ __forceinline__ u64 bcast2(float v) {
    u64 r; asm("mov.b64 %0, {%1, %1};" : "=l"(r) : "f"(v)); return r;
}
__device__ __forceinline__ u64 fma2(u64 a, u64 b, u64 c) {
    u64 d; asm("fma.rn.f32x2 %0, %1, %2, %3;" : "=l"(d) : "l"(a), "l"(b), "l"(c)); return d;
}
__device__ __forceinline__ float2 unpack2(u64 v) {
    float2 r; asm("mov.b64 {%0, %1}, %2;" : "=f"(r.x), "=f"(r.y) : "l"(v)); return r;
}

// ---- cp.async ----
__device__ __forceinline__ void cp_async16(void* smem_dst, const void* gmem_src) {
    uint32_t s;
    asm("{ .reg .u64 t; cvta.to.shared.u64 t, %1; cvt.u32.u64 %0, t; }"
        : "=r"(s) : "l"(smem_dst));
    asm volatile("cp.async.ca.shared.global [%0], [%1], 16;"
                 :: "r"(s), "l"(gmem_src) : "memory");
}
__device__ __forceinline__ void cp_async_commit() {
    asm volatile("cp.async.commit_group;" ::: "memory");
}
template <int N>
__device__ __forceinline__ void cp_async_wait() {
    asm volatile("cp.async.wait_group %0;" :: "n"(N) : "memory");
}

__global__ void __launch_bounds__(32, 1)
rnn_relu_kernel(const float* __restrict__ x,      // [SEQ, BATCH, 4]
                const float* __restrict__ h0,     // [1, BATCH, 3]
                const float* __restrict__ W_ih,   // [3, 4]
                const float* __restrict__ W_hh,   // [3, 3]
                const float* __restrict__ b_ih,   // [3]
                const float* __restrict__ b_hh,   // [3]
                float* __restrict__ out)
{
    // One warp per block; each thread owns one batch chain and its own smem lane.
    __shared__ float4 xs[STAGES][UNR][32];   // 32 KB

    const int lane = threadIdx.x;
    const int b = blockIdx.x * 32 + lane;

    // Pre-pack weights: hidden units (0,1) as f32x2 pairs, unit 2 scalar.
    u64 wih01[IN], whh01[HID];
    float wih2[IN], whh2[HID];
#pragma unroll
    for (int i = 0; i < IN; i++) {
        wih01[i] = pack2(W_ih[0 * IN + i], W_ih[1 * IN + i]);
        wih2[i]  = W_ih[2 * IN + i];
    }
#pragma unroll
    for (int i = 0; i < HID; i++) {
        whh01[i] = pack2(W_hh[0 * HID + i], W_hh[1 * HID + i]);
        whh2[i]  = W_hh[2 * HID + i];
    }
    const u64   bias01 = pack2(b_ih[0] + b_hh[0], b_ih[1] + b_hh[1]);
    const float bias2  = b_ih[2] + b_hh[2];

    float ha = h0[b * HID + 0];
    float hb = h0[b * HID + 1];
    float hc = h0[b * HID + 2];

    const float4* __restrict__ xv = (const float4*)x;  // [SEQ][BATCH]
    float* __restrict__ outs  = out;
    float* __restrict__ hlast = out + (size_t)SEQ * BATCH * HID;

    // Prime STAGES-1 = 3 stages (48 timesteps of lookahead).
#pragma unroll
    for (int s = 0; s < STAGES - 1; s++) {
#pragma unroll
        for (int k = 0; k < UNR; k++)
            cp_async16(&xs[s][k][lane], &xv[(size_t)(s * UNR + k) * BATCH + b]);
        cp_async_commit();
    }

    for (int g = 0; g < NGRP; g++) {
        const int stage = g & (STAGES - 1);

        // This stage's group must be complete (self-written smem; no sync needed).
        cp_async_wait<STAGES - 2>();

        const int t0 = g * UNR;
#pragma unroll
        for (int k = 0; k < UNR; k++) {
            const float4 xt = xs[stage][k][lane];

            // Input projection (off the serial chain): units (0,1) packed.
            u64 p01 = fma2(wih01[0], bcast2(xt.x), bias01);
            p01 = fma2(wih01[1], bcast2(xt.y), p01);
            p01 = fma2(wih01[2], bcast2(xt.z), p01);
            p01 = fma2(wih01[3], bcast2(xt.w), p01);
            float p2 = fmaf(wih2[0], xt.x, bias2);
            p2 = fmaf(wih2[1], xt.y, p2);
            p2 = fmaf(wih2[2], xt.z, p2);
            p2 = fmaf(wih2[3], xt.w, p2);

            // Recurrent update (serial chain: 3 FFMA2/FFMA + max ≈ 16 cyc).
            u64 a01 = fma2(whh01[0], bcast2(ha), p01);
            a01 = fma2(whh01[1], bcast2(hb), a01);
            a01 = fma2(whh01[2], bcast2(hc), a01);
            float a2 = fmaf(whh2[0], ha, p2);
            a2 = fmaf(whh2[1], hb, a2);
            a2 = fmaf(whh2[2], hc, a2);

            const float2 a = unpack2(a01);
            ha = fmaxf(a.x, 0.0f);
            hb = fmaxf(a.y, 0.0f);
            hc = fmaxf(a2, 0.0f);

            const size_t o = ((size_t)(t0 + k) * BATCH + b) * HID;
            __stcs(outs + o + 0, ha);   // streaming: never re-read
            __stcs(outs + o + 1, hb);
            __stcs(outs + o + 2, hc);
        }

        // Refill this stage for group g + STAGES - 1.
        const int gnext = g + STAGES - 1;
        if (gnext < NGRP) {
            const int ns = gnext & (STAGES - 1);
#pragma unroll
            for (int k = 0; k < UNR; k++)
                cp_async16(&xs[ns][k][lane],
                           &xv[(size_t)(gnext * UNR + k) * BATCH + b]);
        }
        cp_async_commit();  // uniform group accounting on the tail
    }

    hlast[b * HID + 0] = ha;
    hlast[b * HID + 1] = hb;
    hlast[b * HID + 2] = hc;
}

extern "C" void kernel_launch(void* const* d_in, const int* in_sizes, int n_in,
                              void* d_out, int out_size)
{
    const float* x    = (const float*)d_in[0];
    const float* h0   = (const float*)d_in[1];
    const float* W_ih = (const float*)d_in[2];
    const float* W_hh = (const float*)d_in[3];
    const float* b_ih = (const float*)d_in[4];
    const float* b_hh = (const float*)d_in[5];
    float* out = (float*)d_out;

    rnn_relu_kernel<<<BATCH / 32, 32>>>(x, h0, W_ih, W_hh, b_ih, b_hh, out);
}